// round 8
// baseline (speedup 1.0000x reference)
#include <cuda_runtime.h>

typedef unsigned long long ull;

// Problem constants
#define BSZ   4096
#define PSZ   32
#define EMB   128
#define HDIM  768
#define MROWS 16            // batch rows per MLP block
#define CHUNK 2048          // batch rows per overlap chunk

// Scratch: intermediate H [B, 768] (12.6 MB)
__device__ float g_H[BSZ * HDIM];

// ── packed f32x2 helpers ────────────────────────────────────────────────
__device__ __forceinline__ ull mul2(ull a, ull b) {
    ull d; asm("mul.rn.f32x2 %0, %1, %2;" : "=l"(d) : "l"(a), "l"(b)); return d;
}
__device__ __forceinline__ ull fma2c(ull a, ull b, ull c) {
    ull d; asm("fma.rn.f32x2 %0, %1, %2, %3;" : "=l"(d) : "l"(a), "l"(b), "l"(c)); return d;
}
__device__ __forceinline__ void fma2acc(ull& d, ull a, ull b) {
    asm("fma.rn.f32x2 %0, %1, %2, %0;" : "+l"(d) : "l"(a), "l"(b));
}
__device__ __forceinline__ ull relu2(ull v) {
    float lo = __uint_as_float((unsigned int)v);
    float hi = __uint_as_float((unsigned int)(v >> 32));
    lo = fmaxf(lo, 0.f); hi = fmaxf(hi, 0.f);
    ull d; asm("mov.b64 %0, {%1, %2};" : "=l"(d) : "f"(lo), "f"(hi)); return d;
}
__device__ __forceinline__ ull dup2(float f) {
    ull d; asm("mov.b64 %0, {%1, %1};" : "=l"(d) : "f"(f)); return d;
}
__device__ __forceinline__ ulonglong2 relu_step2(ulonglong2 x, ulonglong2 w,
                                                 ulonglong2 y, ulonglong2 bm) {
    ulonglong2 t;
    t.x = relu2(fma2c(mul2(x.x, w.x), y.x, bm.x));
    t.y = relu2(fma2c(mul2(x.y, w.y), y.y, bm.y));
    return t;
}

struct PathSmem {
    float sW[3 * EMB];
    float sB[3 * EMB];
    float sAcc[8][256];
    float sCnt[8];
};

// One block per (batch row, group). 8 warps; warp w handles paths
// p = w, w+8, w+16, w+24 with 1-path lookahead prefetch; lane owns 4 dims.
template<int L>
__device__ __forceinline__ void path_body(
    PathSmem& sm,
    const int*   __restrict__ ents,
    const int*   __restrict__ mids,
    const float* __restrict__ counts,
    const float* __restrict__ E,
    const float* __restrict__ Wm,
    const float* __restrict__ Bm,
    int gofs, int bofs)
{
    const int b    = bofs + blockIdx.x;
    const int tid  = threadIdx.x;
    const int wid  = tid >> 5;
    const int lane = tid & 31;

    for (int i = tid; i < 3 * EMB; i += 256) { sm.sW[i] = Wm[i]; sm.sB[i] = Bm[i]; }
    __syncthreads();

    int   e[4][L + 1];
    int   m[4][L];
    float cnt[4];
    #pragma unroll
    for (int pp = 0; pp < 4; pp++) {
        const long base = (long)b * PSZ + (wid + pp * 8);
        const int* ep = ents + base * (L + 1);
        const int* mp = mids + base * L;
        #pragma unroll
        for (int i = 0; i <= L; i++) e[pp][i] = ep[i];
        #pragma unroll
        for (int i = 0; i < L; i++)  m[pp][i] = mp[i];
        cnt[pp] = counts[base];
    }

    ulonglong2 a1; a1.x = 0ull; a1.y = 0ull;
    ulonglong2 a2; a2.x = 0ull; a2.y = 0ull;
    float cs = 0.f;

    ulonglong2 buf[2][L + 1];
    #pragma unroll
    for (int i = 0; i <= L; i++)
        buf[0][i] = *(const ulonglong2*)(E + (long)e[0][i] * EMB + lane * 4);

    #pragma unroll
    for (int pp = 0; pp < 4; pp++) {
        if (pp < 3) {
            #pragma unroll
            for (int i = 0; i <= L; i++)
                buf[(pp + 1) & 1][i] =
                    *(const ulonglong2*)(E + (long)e[pp + 1][i] * EMB + lane * 4);
        }
        ulonglong2 (&rows)[L + 1] = buf[pp & 1];

        // forward
        ulonglong2 x = rows[0];
        #pragma unroll
        for (int i = 0; i < L; i++) {
            const ulonglong2 w  = *(const ulonglong2*)(sm.sW + m[pp][i] * EMB + lane * 4);
            const ulonglong2 bb = *(const ulonglong2*)(sm.sB + m[pp][i] * EMB + lane * 4);
            x = relu_step2(x, w, rows[i + 1], bb);
        }
        const ulonglong2 o1 = x;

        // backward: start x and (stale) y are both E[ents[L]]
        const ulonglong2 yl = rows[L];
        x = yl;
        #pragma unroll
        for (int i = L - 1; i >= 0; i--) {
            const ulonglong2 w  = *(const ulonglong2*)(sm.sW + m[pp][i] * EMB + lane * 4);
            const ulonglong2 bb = *(const ulonglong2*)(sm.sB + m[pp][i] * EMB + lane * 4);
            x = relu_step2(x, w, yl, bb);
        }

        const ull c2 = dup2(cnt[pp]);
        fma2acc(a1.x, o1.x, c2); fma2acc(a1.y, o1.y, c2);
        fma2acc(a2.x, x.x,  c2); fma2acc(a2.y, x.y,  c2);
        cs += cnt[pp];
    }

    ((ulonglong2*)sm.sAcc[wid])[lane]                 = a1;  // dims 0..127
    *((ulonglong2*)(sm.sAcc[wid] + 128) + lane)       = a2;  // dims 128..255
    if (lane == 0) sm.sCnt[wid] = cs;
    __syncthreads();

    float s = 0.f, csum = 0.f;
    #pragma unroll
    for (int w = 0; w < 8; w++) { s += sm.sAcc[w][tid]; csum += sm.sCnt[w]; }
    g_H[(long)b * HDIM + gofs + tid] = s / csum;
}

__global__ __launch_bounds__(256) void paths_kernel(
    const int* __restrict__ ent1, const int* __restrict__ mid1, const float* __restrict__ c1,
    const int* __restrict__ ent2, const int* __restrict__ mid2, const float* __restrict__ c2,
    const int* __restrict__ ent3, const int* __restrict__ mid3, const float* __restrict__ c3,
    const float* __restrict__ E, const float* __restrict__ Wm, const float* __restrict__ Bm,
    int bofs)
{
    __shared__ PathSmem sm;
    const int g = blockIdx.y;
    if (g == 0)      path_body<1>(sm, ent1, mid1, c1, E, Wm, Bm, 0,   bofs);
    else if (g == 1) path_body<2>(sm, ent2, mid2, c2, E, Wm, Bm, 256, bofs);
    else             path_body<3>(sm, ent3, mid3, c3, E, Wm, Bm, 512, bofs);
}

// ────────────────────────────────────────────────────────────────────────
// MLP head (R5 version): 16 rows/block, 512 threads, batch-offset chunked.
// H tile transposed + 16B-granule swizzled in smem; phase A uses f32x2.
// ────────────────────────────────────────────────────────────────────────
__global__ __launch_bounds__(512, 2) void mlp_kernel(
    const float* __restrict__ W1, const float* __restrict__ b1,
    const float* __restrict__ W2, const float* __restrict__ b2,
    const float* __restrict__ W3, const float* __restrict__ b3,
    float* __restrict__ out, int b0base)
{
    __shared__ float sHt[HDIM * MROWS];   // 48 KB exactly; reused after phase A

    const int b0  = b0base + blockIdx.x * MROWS;
    const int tid = threadIdx.x;

    // ── Load + transpose H tile (swizzled) ──────────────────────────────
    {
        const float4* src = (const float4*)(g_H + (long)b0 * HDIM);
        #pragma unroll
        for (int i = 0; i < 6; i++) {
            const int idx = tid + i * 512;        // 0..3071 float4s
            const float4 v = src[idx];
            const int r  = idx / (HDIM / 4);
            const int kq = idx % (HDIM / 4);
            const int g  = r >> 2, r3 = r & 3;
            const float vv[4] = {v.x, v.y, v.z, v.w};
            #pragma unroll
            for (int j = 0; j < 4; j++) {
                const int k  = kq * 4 + j;
                const int gp = g ^ (k & 3);
                sHt[k * 16 + gp * 4 + r3] = vv[j];
            }
        }
    }
    __syncthreads();

    // ── Phase A: h1 = relu(H @ W1 + b1) with f32x2, K split in halves ───
    const int c  = tid & 127;
    const int kh = (tid >> 7) & 1;
    const int rg = tid >> 8;              // 0: rows 0-7, 1: rows 8-15
    const int gA = rg * 2, gB = rg * 2 + 1;

    ull a0 = 0ull, a1 = 0ull, a2 = 0ull, a3 = 0ull;

    {
        const float* w1p = W1 + (long)(kh * 384) * 128 + c;
        const int kbase0 = kh * 384;
        #pragma unroll 2
        for (int kk = 0; kk < 384; kk += 4) {
            float w[4];
            #pragma unroll
            for (int j = 0; j < 4; j++) w[j] = __ldg(w1p + (kk + j) * 128);
            #pragma unroll
            for (int j = 0; j < 4; j++) {
                const int k = kbase0 + kk + j;    // k & 3 == j (compile-time)
                const ull w2 = dup2(w[j]);
                const float* base = sHt + k * 16;
                const ulonglong2 vA = *(const ulonglong2*)(base + ((gA ^ j) << 2));
                const ulonglong2 vB = *(const ulonglong2*)(base + ((gB ^ j) << 2));
                fma2acc(a0, vA.x, w2);
                fma2acc(a1, vA.y, w2);
                fma2acc(a2, vB.x, w2);
                fma2acc(a3, vB.y, w2);
            }
        }
    }

    float af[8];
    {
        const ull av[4] = {a0, a1, a2, a3};
        #pragma unroll
        for (int i = 0; i < 4; i++) {
            af[2 * i]     = __uint_as_float((unsigned int)av[i]);
            af[2 * i + 1] = __uint_as_float((unsigned int)(av[i] >> 32));
        }
    }
    __syncthreads();                       // all done reading sHt

    float* const scratch = sHt;                    // [8][256]
    float* const sh1     = sHt + 2048;             // [16][128]
    float* const sh2     = sHt + 4096;             // [16][32]

    const int slot = rg * 128 + c;
    if (kh == 1) {
        #pragma unroll
        for (int i = 0; i < 8; i++) scratch[i * 256 + slot] = af[i];
    }
    __syncthreads();
    if (kh == 0) {
        const float bias = b1[c];
        #pragma unroll
        for (int i = 0; i < 8; i++) {
            const float v = af[i] + scratch[i * 256 + slot] + bias;
            sh1[(rg * 8 + i) * 128 + c] = fmaxf(v, 0.f);
        }
    }
    __syncthreads();

    // ── Phase B: h2 = relu(h1 @ W2 + b2) — 512 thr = 16 rows × 32 cols ──
    {
        const int r  = tid >> 5;
        const int c2 = tid & 31;
        float a = b2[c2];
        #pragma unroll 8
        for (int k = 0; k < 128; k += 4) {
            const float4 hv = *(const float4*)(sh1 + r * 128 + k);
            a = fmaf(hv.x, __ldg(W2 + (k    ) * 32 + c2), a);
            a = fmaf(hv.y, __ldg(W2 + (k + 1) * 32 + c2), a);
            a = fmaf(hv.z, __ldg(W2 + (k + 2) * 32 + c2), a);
            a = fmaf(hv.w, __ldg(W2 + (k + 3) * 32 + c2), a);
        }
        sh2[r * 32 + c2] = fmaxf(a, 0.f);
    }
    __syncthreads();

    // ── Phase C: out = h2 @ W3 + b3 ─────────────────────────────────────
    if (tid < MROWS) {
        float a = b3[0];
        #pragma unroll
        for (int k = 0; k < 32; k++) a = fmaf(sh2[tid * 32 + k], W3[k], a);
        out[b0 + tid] = a;
    }
}

extern "C" void kernel_launch(void* const* d_in, const int* in_sizes, int n_in,
                              void* d_out, int out_size)
{
    // Side stream + events: created ONCE on the first (correctness) call,
    // before graph capture ever happens. Only capturable ops (launch, record,
    // wait; DisableTiming events) are issued on subsequent calls.
    static cudaStream_t s2  = nullptr;
    static cudaEvent_t  evA = nullptr, evJ = nullptr;
    if (s2 == nullptr) {
        cudaStreamCreateWithFlags(&s2, cudaStreamNonBlocking);
        cudaEventCreateWithFlags(&evA, cudaEventDisableTiming);
        cudaEventCreateWithFlags(&evJ, cudaEventDisableTiming);
    }

    const bool dictOrder = (in_sizes[2] == BSZ * PSZ);

    const int *ent1, *mid1, *ent2, *mid2, *ent3, *mid3;
    const float *c1, *c2, *c3;
    if (dictOrder) {
        ent1 = (const int*)d_in[0]; mid1 = (const int*)d_in[1]; c1 = (const float*)d_in[2];
        ent2 = (const int*)d_in[3]; mid2 = (const int*)d_in[4]; c2 = (const float*)d_in[5];
        ent3 = (const int*)d_in[6]; mid3 = (const int*)d_in[7]; c3 = (const float*)d_in[8];
    } else {
        ent1 = (const int*)d_in[0]; mid1 = (const int*)d_in[1];
        ent2 = (const int*)d_in[2]; mid2 = (const int*)d_in[3];
        ent3 = (const int*)d_in[4]; mid3 = (const int*)d_in[5];
        c1 = (const float*)d_in[6]; c2 = (const float*)d_in[7]; c3 = (const float*)d_in[8];
    }
    const float* E  = (const float*)d_in[9];
    const float* Wm = (const float*)d_in[10];
    const float* Bm = (const float*)d_in[11];
    const float* W1 = (const float*)d_in[12];
    const float* b1 = (const float*)d_in[13];
    const float* W2 = (const float*)d_in[14];
    const float* b2 = (const float*)d_in[15];
    const float* W3 = (const float*)d_in[16];
    const float* b3 = (const float*)d_in[17];

    float* out = (float*)d_out;
    const dim3 pgrid(CHUNK, 3);
    const cudaStream_t s0 = (cudaStream_t)0;   // legacy default stream

    // chunk A paths (stream 0)
    paths_kernel<<<pgrid, 256, 0, s0>>>(ent1, mid1, c1, ent2, mid2, c2,
                                        ent3, mid3, c3, E, Wm, Bm, 0);
    cudaEventRecord(evA, s0);
    cudaStreamWaitEvent(s2, evA, 0);

    // chunk A mlp on side stream — overlaps chunk B paths
    mlp_kernel<<<CHUNK / MROWS, 512, 0, s2>>>(W1, b1, W2, b2, W3, b3, out, 0);

    // chunk B paths + mlp (stream 0, ordered)
    paths_kernel<<<pgrid, 256, 0, s0>>>(ent1, mid1, c1, ent2, mid2, c2,
                                        ent3, mid3, c3, E, Wm, Bm, CHUNK);
    mlp_kernel<<<CHUNK / MROWS, 512, 0, s0>>>(W1, b1, W2, b2, W3, b3, out, CHUNK);

    // join side stream back into stream 0
    cudaEventRecord(evJ, s2);
    cudaStreamWaitEvent(s0, evJ, 0);
}